// round 8
// baseline (speedup 1.0000x reference)
#include <cuda_runtime.h>
#include <cstdint>

#define BB 2
#define HH 8
#define LL 512
#define DD 64
#define TI 4
#define NTHR 512
#define TEMPINV 0.125f

#define OUT_ELEMS  (BB*HH*LL*DD)
#define ATTN_ELEMS (BB*HH*LL*LL)

// 16 MB scratch for base scores qs@k^T ; 16 MB fallback attn buffer
__device__ float g_s0[ATTN_ELEMS];
__device__ float g_attn_fb[ATTN_ELEMS];

// ---------- main kernel smem layout (floats) ----------
#define OFF_QS   0                  // qs[4][8][64] = 2048
#define OFF_MK   2048               // 512
#define OFF_R1   2560               // 64
#define OFF_R2   2624               // 64
#define OFF_BUF  2688               // double buffers
#define SM1_TILE (4*64*68)          // 17408 (phase1 adjk tile, PAD 68)
#define SM2_TILE (4*64*64)          // 16384 (phase2 adjv tile, JT2=64)
#define MAIN_SMEM_FLOATS (OFF_BUF + 2*SM1_TILE)   // 37504 -> 150016 B

// ---------- PTX helpers ----------
__device__ __forceinline__ void cpa16(uint32_t dst, const void* src) {
    asm volatile("cp.async.cg.shared.global [%0], [%1], 16;" :: "r"(dst), "l"(src) : "memory");
}
#define CP_COMMIT asm volatile("cp.async.commit_group;" ::: "memory")
#define CP_WAIT1  asm volatile("cp.async.wait_group 1;" ::: "memory")
#define CP_WAIT0  asm volatile("cp.async.wait_group 0;" ::: "memory")

__device__ __forceinline__ void fma2(unsigned long long& d,
                                     unsigned long long a, unsigned long long b) {
    asm("fma.rn.f32x2 %0, %1, %2, %0;" : "+l"(d) : "l"(a), "l"(b));
}
__device__ __forceinline__ float hadd2(unsigned long long v) {
    float lo, hi;
    asm("mov.b64 {%0,%1}, %2;" : "=f"(lo), "=f"(hi) : "l"(v));
    return lo + hi;
}
__device__ __forceinline__ unsigned long long pack2(float lo, float hi) {
    unsigned long long r;
    asm("mov.b64 %0, {%1,%2};" : "=l"(r) : "f"(lo), "f"(hi));
    return r;
}
__device__ __forceinline__ void unpack2(float& lo, float& hi, unsigned long long v) {
    asm("mov.b64 {%0,%1}, %2;" : "=f"(lo), "=f"(hi) : "l"(v));
}
__device__ __forceinline__ float warp_max(float x) {
#pragma unroll
    for (int o = 16; o; o >>= 1) x = fmaxf(x, __shfl_xor_sync(0xffffffffu, x, o));
    return x;
}
__device__ __forceinline__ float warp_sum(float x) {
#pragma unroll
    for (int o = 16; o; o >>= 1) x += __shfl_xor_sync(0xffffffffu, x, o);
    return x;
}

// =====================================================================
// Kernel 1: QK base scores. g_s0[bh,i,j] = (q/8)[bh,i,:] . k[bh,j,:]
// grid 256 = 16 bh x (4 itile x 4 jtile of 128x128), 256 thr, 8x8 micro
// (exact R6 version — 20.7us measured)
// =====================================================================
#define QK_PADI 132
#define QK_SMEM_FLOATS (2*64*QK_PADI)   // 16896 -> 67584 B

__global__ void __launch_bounds__(256, 2)
qk_kernel(const float* __restrict__ q, const float* __restrict__ k)
{
    extern __shared__ float smq[];
    float* qT = smq;                 // [64 d][132]
    float* kT = smq + 64 * QK_PADI;  // [64 d][132]
    const int bid = blockIdx.x;
    const int bh = bid >> 4;
    const int it = (bid >> 2) & 3, jt = bid & 3;
    const int i0 = it * 128, j0 = jt * 128;
    const int tid = threadIdx.x;

    const float* qb = q + ((size_t)bh * LL + i0) * DD;
    const float* kb = k + ((size_t)bh * LL + j0) * DD;
#pragma unroll
    for (int f = tid; f < 128 * 64; f += 256) {
        int i = f >> 6, d = f & 63;
        qT[d * QK_PADI + i] = qb[(size_t)i * DD + d] * TEMPINV;
        kT[d * QK_PADI + i] = kb[(size_t)i * DD + d];
    }
    __syncthreads();

    const int ty = tid >> 4, tx = tid & 15;
    const int il = ty * 8, jl = tx * 8;
    unsigned long long acc[8][4];
#pragma unroll
    for (int r = 0; r < 8; r++)
#pragma unroll
        for (int c = 0; c < 4; c++) acc[r][c] = 0ull;

#pragma unroll 4
    for (int d = 0; d < 64; d++) {
        float4 a0 = *reinterpret_cast<const float4*>(qT + d * QK_PADI + il);
        float4 a1 = *reinterpret_cast<const float4*>(qT + d * QK_PADI + il + 4);
        const ulonglong2* bp = reinterpret_cast<const ulonglong2*>(kT + d * QK_PADI + jl);
        ulonglong2 b01 = bp[0], b23 = bp[1];
        float a[8] = {a0.x,a0.y,a0.z,a0.w,a1.x,a1.y,a1.z,a1.w};
#pragma unroll
        for (int r = 0; r < 8; r++) {
            unsigned long long ar = pack2(a[r], a[r]);
            fma2(acc[r][0], ar, b01.x);
            fma2(acc[r][1], ar, b01.y);
            fma2(acc[r][2], ar, b23.x);
            fma2(acc[r][3], ar, b23.y);
        }
    }

#pragma unroll
    for (int r = 0; r < 8; r++) {
        float c[8];
#pragma unroll
        for (int c2 = 0; c2 < 4; c2++) unpack2(c[2*c2], c[2*c2+1], acc[r][c2]);
        float* dst = g_s0 + ((size_t)bh * LL + i0 + il + r) * LL + j0 + jl;
        float4 v0 = {c[0], c[1], c[2], c[3]};
        float4 v1 = {c[4], c[5], c[6], c[7]};
        *reinterpret_cast<float4*>(dst)     = v0;
        *reinterpret_cast<float4*>(dst + 4) = v1;
    }
}

// =====================================================================
// Kernel 2 (main): adj-score accumulation + softmax + adj_v weighted sum
// grid 256 = (b, i-tile of 4 rows), 512 thr
// R6 + q-register cache for rows 0,1 of each warp's 4-row block
// =====================================================================
__global__ void __launch_bounds__(NTHR, 1)
main_kernel(const float* __restrict__ q, const float* __restrict__ adjk,
            const float* __restrict__ adjv, const int* __restrict__ mask,
            float* __restrict__ out, float* __restrict__ attn_ext, int write_ext)
{
    extern __shared__ float sm[];
    float* attn = write_ext ? attn_ext : g_attn_fb;

    const int bid  = blockIdx.x;
    const int b    = bid / (LL / TI);
    const int i0   = (bid % (LL / TI)) * TI;
    const int tid  = threadIdx.x;
    const int w    = tid >> 5;
    const int lane = tid & 31;

    float* qs = sm + OFF_QS;
    float* mk = sm + OFF_MK;
    float* r1 = sm + OFF_R1;
    float* r2 = sm + OFF_R2;
    const uint32_t smemU = (uint32_t)__cvta_generic_to_shared(sm);

    // ---- phase 0: qs (scaled q) + mask flags ----
    {
        int d4 = tid & 15, h = (tid >> 4) & 7, ti = tid >> 7;
        float4 val = *reinterpret_cast<const float4*>(
            &q[((size_t)(b * HH + h) * LL + i0 + ti) * DD + d4 * 4]);
        val.x *= TEMPINV; val.y *= TEMPINV; val.z *= TEMPINV; val.w *= TEMPINV;
        reinterpret_cast<float4*>(qs)[(ti * HH + h) * (DD / 4) + d4] = val;
        mk[tid] = (mask[b * LL + tid] != 0) ? 1.0f : 0.0f;
    }

    // warp mapping phase 1: ti, jh (j half of 64), hg (head group of 4)
    const int ti  = w >> 2;
    const int sub = w & 3;
    const int jh  = sub >> 1;
    const int hg  = sub & 1;
    const int h0  = hg * 4;
    const int jj  = jh * 32 + lane;          // 0..63 within tile
    const int rbase = ti * HH + h0;          // row 0..31

    const float* adjk_b = adjk + ((size_t)(b * LL + i0) * LL) * DD;
    const float* adjv_b = adjv + ((size_t)(b * LL + i0) * LL) * DD;

    // prologue: stage phase-1 tile 0
    {
        const float* srcb = adjk_b;
#pragma unroll
        for (int s2 = 0; s2 < 8; s2++) {
            int f = tid + s2 * NTHR;
            int d4 = f & 15, jjx = (f >> 4) & 63, ti2 = f >> 10;
            cpa16(smemU + (uint32_t)(OFF_BUF + (ti2 * 64 + jjx) * 68 + d4 * 4) * 4,
                  srcb + (size_t)ti2 * (LL * DD) + (size_t)jjx * DD + d4 * 4);
        }
        CP_COMMIT;
    }

    // init scores from g_s0
    float s[4][8];
#pragma unroll
    for (int hh = 0; hh < 4; hh++)
#pragma unroll
        for (int t = 0; t < 8; t++)
            s[hh][t] = g_s0[((size_t)(b * HH + h0 + hh) * LL + i0 + ti) * LL + t * 64 + jj];

    // qs must be fully staged before the register preload
    __syncthreads();

    // cache q rows rbase+0, rbase+1 in registers (loop-invariant across tiles)
    unsigned long long qr0[32], qr1[32];
    {
        const unsigned long long* p0 =
            reinterpret_cast<const unsigned long long*>(qs + (rbase + 0) * DD);
        const unsigned long long* p1 =
            reinterpret_cast<const unsigned long long*>(qs + (rbase + 1) * DD);
#pragma unroll
        for (int i = 0; i < 32; i++) { qr0[i] = p0[i]; qr1[i] = p1[i]; }
    }
    const ulonglong2* q2p = reinterpret_cast<const ulonglong2*>(qs + (rbase + 2) * DD);
    const ulonglong2* q3p = reinterpret_cast<const ulonglong2*>(qs + (rbase + 3) * DD);

    // ---- phase 1: 8 tiles of 64 j, double-buffered ----
#pragma unroll
    for (int t = 0; t < 8; t++) {
        if (t < 7) {
            const float* srcb = adjk_b + (size_t)(t + 1) * 64 * DD;
            const int base = OFF_BUF + ((t + 1) & 1) * SM1_TILE;
#pragma unroll
            for (int s2 = 0; s2 < 8; s2++) {
                int f = tid + s2 * NTHR;
                int d4 = f & 15, jjx = (f >> 4) & 63, ti2 = f >> 10;
                cpa16(smemU + (uint32_t)(base + (ti2 * 64 + jjx) * 68 + d4 * 4) * 4,
                      srcb + (size_t)ti2 * (LL * DD) + (size_t)jjx * DD + d4 * 4);
            }
            CP_COMMIT;
            CP_WAIT1;
        } else {
            CP_WAIT0;
        }
        __syncthreads();

        const float* bufp = sm + OFF_BUF + (t & 1) * SM1_TILE;
        const ulonglong2* ap = reinterpret_cast<const ulonglong2*>(bufp + (ti * 64 + jj) * 68);
        unsigned long long a0 = 0ull, a1 = 0ull, a2 = 0ull, a3 = 0ull;
#pragma unroll
        for (int d4 = 0; d4 < 16; d4++) {
            ulonglong2 ad = ap[d4];
            fma2(a0, qr0[2*d4],   ad.x); fma2(a0, qr0[2*d4+1], ad.y);
            fma2(a1, qr1[2*d4],   ad.x); fma2(a1, qr1[2*d4+1], ad.y);
            ulonglong2 v2 = q2p[d4]; fma2(a2, v2.x, ad.x); fma2(a2, v2.y, ad.y);
            ulonglong2 v3 = q3p[d4]; fma2(a3, v3.x, ad.x); fma2(a3, v3.y, ad.y);
        }
        s[0][t] += hadd2(a0); s[1][t] += hadd2(a1);
        s[2][t] += hadd2(a2); s[3][t] += hadd2(a3);
        __syncthreads();
    }

    // prologue: stage phase-2 tile 0 (JT2=64) into buffer 0 (dead now)
#pragma unroll
    for (int s2 = 0; s2 < 8; s2++) {
        int f = tid + s2 * NTHR;
        int d4 = f & 15, jx = (f >> 4) & 63, ti2 = f >> 10;
        cpa16(smemU + (uint32_t)(OFF_BUF + (ti2 * 64 + jx) * 64 + d4 * 4) * 4,
              adjv_b + (size_t)ti2 * (LL * DD) + (size_t)jx * DD + d4 * 4);
    }
    CP_COMMIT;

    // ---- softmax (mask -> max -> exp -> norm) ----
    float m[4] = {-3.4e38f, -3.4e38f, -3.4e38f, -3.4e38f};
#pragma unroll
    for (int t = 0; t < 8; t++) {
        bool live = mk[t * 64 + jj] != 0.0f;
#pragma unroll
        for (int hh = 0; hh < 4; hh++) {
            float x = live ? s[hh][t] : -10000.0f;
            s[hh][t] = x;
            m[hh] = fmaxf(m[hh], x);
        }
    }
#pragma unroll
    for (int hh = 0; hh < 4; hh++) m[hh] = warp_max(m[hh]);
    if (lane == 0) {
#pragma unroll
        for (int hh = 0; hh < 4; hh++) r1[(rbase + hh) * 2 + jh] = m[hh];
    }
    __syncthreads();
#pragma unroll
    for (int hh = 0; hh < 4; hh++)
        m[hh] = fmaxf(r1[(rbase + hh) * 2], r1[(rbase + hh) * 2 + 1]);

    float sum[4] = {0.f, 0.f, 0.f, 0.f};
#pragma unroll
    for (int t = 0; t < 8; t++)
#pragma unroll
        for (int hh = 0; hh < 4; hh++) {
            float e = __expf(s[hh][t] - m[hh]);
            s[hh][t] = e;
            sum[hh] += e;
        }
#pragma unroll
    for (int hh = 0; hh < 4; hh++) sum[hh] = warp_sum(sum[hh]);
    if (lane == 0) {
#pragma unroll
        for (int hh = 0; hh < 4; hh++) r2[(rbase + hh) * 2 + jh] = sum[hh];
    }
    __syncthreads();
    float inv[4];
#pragma unroll
    for (int hh = 0; hh < 4; hh++)
        inv[hh] = 1.0f / (r2[(rbase + hh) * 2] + r2[(rbase + hh) * 2 + 1]);

    // write p to attn (gmem only; phase 2 reads it back via L1/L2-hot LDG)
#pragma unroll
    for (int hh = 0; hh < 4; hh++) {
        float* arow = attn + ((size_t)(b * HH + h0 + hh) * LL + i0 + ti) * LL;
#pragma unroll
        for (int t = 0; t < 8; t++) {
            int j = t * 64 + jj;
            arow[j] = s[hh][t] * inv[hh];
        }
    }
    // make attn writes visible to all warps before phase-2 reads
    __syncthreads();

    // ---- phase 2: out_adj = sum_j p * adj_v, 8 tiles of 64 j ----
    const int ti2w = w >> 2;
    const int js   = w & 3;
    const int l2   = lane * 2;

    const float* arp[8];
#pragma unroll
    for (int r = 0; r < 8; r++)
        arp[r] = attn + ((size_t)(b * HH + r) * LL + i0 + ti2w) * LL;

    float2 o[8];
#pragma unroll
    for (int h = 0; h < 8; h++) { o[h].x = 0.f; o[h].y = 0.f; }

#pragma unroll 1
    for (int t2 = 0; t2 < 8; t2++) {
        if (t2 < 7) {
            const float* srcb = adjv_b + (size_t)(t2 + 1) * 64 * DD;
            const int base = OFF_BUF + ((t2 + 1) & 1) * SM2_TILE;
#pragma unroll
            for (int s2 = 0; s2 < 8; s2++) {
                int f = tid + s2 * NTHR;
                int d4 = f & 15, jx = (f >> 4) & 63, tq = f >> 10;
                cpa16(smemU + (uint32_t)(base + (tq * 64 + jx) * 64 + d4 * 4) * 4,
                      srcb + (size_t)tq * (LL * DD) + (size_t)jx * DD + d4 * 4);
            }
            CP_COMMIT;
            CP_WAIT1;
        } else {
            CP_WAIT0;
        }
        __syncthreads();

        const float* pb = sm + OFF_BUF + (t2 & 1) * SM2_TILE;
#pragma unroll
        for (int x4 = 0; x4 < 4; x4++) {
            const int jb = js * 16 + x4 * 4;
            const int j  = t2 * 64 + jb;
            float4 p[8];
#pragma unroll
            for (int r = 0; r < 8; r++)
                p[r] = *reinterpret_cast<const float4*>(arp[r] + j);
            float2 av0 = *reinterpret_cast<const float2*>(pb + (ti2w * 64 + jb + 0) * 64 + l2);
            float2 av1 = *reinterpret_cast<const float2*>(pb + (ti2w * 64 + jb + 1) * 64 + l2);
            float2 av2 = *reinterpret_cast<const float2*>(pb + (ti2w * 64 + jb + 2) * 64 + l2);
            float2 av3 = *reinterpret_cast<const float2*>(pb + (ti2w * 64 + jb + 3) * 64 + l2);
#pragma unroll
            for (int r = 0; r < 8; r++) {
                o[r].x += p[r].x * av0.x; o[r].y += p[r].x * av0.y;
                o[r].x += p[r].y * av1.x; o[r].y += p[r].y * av1.y;
                o[r].x += p[r].z * av2.x; o[r].y += p[r].z * av2.y;
                o[r].x += p[r].w * av3.x; o[r].y += p[r].w * av3.y;
            }
        }
        __syncthreads();
    }

    // reduce 4 j-splits via smem (overlay on dead buffer 0 region)
    float* ored = sm + OFF_BUF;   // [4 js][32 rows][64 d] = 8192 floats
#pragma unroll
    for (int h = 0; h < 8; h++)
        *reinterpret_cast<float2*>(ored + ((js * 32 + ti2w * 8 + h) * 64) + l2) = o[h];
    __syncthreads();
    {
        int row = tid >> 4, d4 = tid & 15;
        float4 aa = reinterpret_cast<const float4*>(ored + (0 * 32 + row) * 64)[d4];
        float4 bb = reinterpret_cast<const float4*>(ored + (1 * 32 + row) * 64)[d4];
        float4 cc = reinterpret_cast<const float4*>(ored + (2 * 32 + row) * 64)[d4];
        float4 dd = reinterpret_cast<const float4*>(ored + (3 * 32 + row) * 64)[d4];
        float4 r;
        r.x = aa.x + bb.x + cc.x + dd.x;
        r.y = aa.y + bb.y + cc.y + dd.y;
        r.z = aa.z + bb.z + cc.z + dd.z;
        r.w = aa.w + bb.w + cc.w + dd.w;
        int tio = row / HH, h = row % HH;
        *reinterpret_cast<float4*>(
            &out[((size_t)(b * HH + h) * LL + i0 + tio) * DD + d4 * 4]) = r;
    }
}

// =====================================================================
// Kernel 3: out += attn @ v.  grid 256 = 16 bh x 16 i-tiles of 32
// (exact R6 version)
// =====================================================================
__global__ void __launch_bounds__(256, 4)
av_kernel(const float* __restrict__ v, float* __restrict__ out,
          const float* __restrict__ attn_ext, int write_ext)
{
    __shared__ float aS[2][32 * 32];   // [i][j]
    __shared__ float vS[2][32 * 64];   // [j][d]
    const float* attn = write_ext ? attn_ext : g_attn_fb;

    const int bid = blockIdx.x;
    const int bh  = bid >> 4;
    const int i0  = (bid & 15) * 32;
    const int tid = threadIdx.x;
    const uint32_t aU = (uint32_t)__cvta_generic_to_shared(&aS[0][0]);
    const uint32_t vU = (uint32_t)__cvta_generic_to_shared(&vS[0][0]);

    const float* ab = attn + ((size_t)bh * LL + i0) * LL;
    const float* vb = v + (size_t)bh * LL * DD;

    // stage tile 0
    {
        int i = tid >> 3, c = tid & 7;
        cpa16(aU + (uint32_t)(i * 32 + c * 4) * 4, ab + (size_t)i * LL + c * 4);
#pragma unroll
        for (int s2 = 0; s2 < 2; s2++) {
            int f = tid + s2 * 256;
            int j = f >> 4, d4 = f & 15;
            cpa16(vU + (uint32_t)(j * 64 + d4 * 4) * 4, vb + (size_t)j * DD + d4 * 4);
        }
        CP_COMMIT;
    }

    const int ty = tid >> 5, tx = tid & 31;
    float2 o[4];
#pragma unroll
    for (int r = 0; r < 4; r++) { o[r].x = 0.f; o[r].y = 0.f; }

#pragma unroll 1
    for (int kt = 0; kt < 16; kt++) {
        if (kt < 15) {
            int j0 = (kt + 1) * 32;
            int bsel = (kt + 1) & 1;
            int i = tid >> 3, c = tid & 7;
            cpa16(aU + (uint32_t)(bsel * 1024 + i * 32 + c * 4) * 4,
                  ab + (size_t)i * LL + j0 + c * 4);
#pragma unroll
            for (int s2 = 0; s2 < 2; s2++) {
                int f = tid + s2 * 256;
                int j = f >> 4, d4 = f & 15;
                cpa16(vU + (uint32_t)(bsel * 2048 + j * 64 + d4 * 4) * 4,
                      vb + (size_t)(j0 + j) * DD + d4 * 4);
            }
            CP_COMMIT;
            CP_WAIT1;
        } else {
            CP_WAIT0;
        }
        __syncthreads();

        const float* aT = &aS[kt & 1][0];
        const float* vT = &vS[kt & 1][0];
#pragma unroll 4
        for (int j = 0; j < 32; j++) {
            float2 vv = *reinterpret_cast<const float2*>(vT + j * 64 + tx * 2);
            float p0 = aT[(ty * 4 + 0) * 32 + j];
            float p1 = aT[(ty * 4 + 1) * 32 + j];
            float p2 = aT[(ty * 4 + 2) * 32 + j];
            float p3 = aT[(ty * 4 + 3) * 32 + j];
            o[0].x += p0 * vv.x; o[0].y += p0 * vv.y;
            o[1].x += p1 * vv.x; o[1].y += p1 * vv.y;
            o[2].x += p2 * vv.x; o[2].y += p2 * vv.y;
            o[3].x += p3 * vv.x; o[3].y += p3 * vv.y;
        }
        __syncthreads();
    }

#pragma unroll
    for (int r = 0; r < 4; r++) {
        float2* op = reinterpret_cast<float2*>(
            &out[((size_t)bh * LL + i0 + ty * 4 + r) * DD + tx * 2]);
        float2 cur = *op;
        cur.x += o[r].x; cur.y += o[r].y;
        *op = cur;
    }
}

// =====================================================================
extern "C" void kernel_launch(void* const* d_in, const int* in_sizes, int n_in,
                              void* d_out, int out_size)
{
    const float* q    = (const float*)d_in[0];
    const float* k    = (const float*)d_in[1];
    const float* v    = (const float*)d_in[2];
    const float* adjk = (const float*)d_in[3];
    const float* adjv = (const float*)d_in[4];
    const int*   mask = (const int*)d_in[5];
    float* out = (float*)d_out;

    int write_attn = (out_size >= OUT_ELEMS + ATTN_ELEMS) ? 1 : 0;
    float* attn_ext = out + OUT_ELEMS;

    cudaFuncSetAttribute(qk_kernel, cudaFuncAttributeMaxDynamicSharedMemorySize,
                         QK_SMEM_FLOATS * 4);
    cudaFuncSetAttribute(main_kernel, cudaFuncAttributeMaxDynamicSharedMemorySize,
                         MAIN_SMEM_FLOATS * 4);

    qk_kernel<<<256, 256, QK_SMEM_FLOATS * 4>>>(q, k);
    main_kernel<<<BB * (LL / TI), NTHR, MAIN_SMEM_FLOATS * 4>>>(
        q, adjk, adjv, mask, out, attn_ext, write_attn);
    av_kernel<<<256, 256>>>(v, out, attn_ext, write_attn);
}

// round 9
// speedup vs baseline: 1.1993x; 1.1993x over previous
#include <cuda_runtime.h>
#include <cstdint>

#define BB 2
#define HH 8
#define LL 512
#define DD 64
#define TI 4
#define NTHR 512
#define TEMPINV 0.125f

#define OUT_ELEMS  (BB*HH*LL*DD)
#define ATTN_ELEMS (BB*HH*LL*LL)

// 16 MB scratch for base scores qs@k^T ; 16 MB fallback attn buffer
__device__ float g_s0[ATTN_ELEMS];
__device__ float g_attn_fb[ATTN_ELEMS];

// ---------- main kernel smem layout (floats) ----------
#define OFF_QS   0                  // qs[4][8][64] = 2048
#define OFF_MK   2048               // 512
#define OFF_R1   2560               // 64
#define OFF_R2   2624               // 64
#define OFF_BUF  2688               // triple buffers
#define SM1_TILE (4*64*68)          // 17408 (phase1 adjk tile, PAD 68)
#define SM2_TILE (4*64*64)          // 16384 (phase2 adjv tile, JT2=64)
#define MAIN_SMEM_FLOATS (OFF_BUF + 3*SM1_TILE)   // 54912 -> 219648 B

// ---------- PTX helpers ----------
__device__ __forceinline__ void cpa16(uint32_t dst, const void* src) {
    asm volatile("cp.async.cg.shared.global [%0], [%1], 16;" :: "r"(dst), "l"(src) : "memory");
}
#define CP_COMMIT asm volatile("cp.async.commit_group;" ::: "memory")
#define CP_WAIT2  asm volatile("cp.async.wait_group 2;" ::: "memory")
#define CP_WAIT1  asm volatile("cp.async.wait_group 1;" ::: "memory")
#define CP_WAIT0  asm volatile("cp.async.wait_group 0;" ::: "memory")

__device__ __forceinline__ void fma2(unsigned long long& d,
                                     unsigned long long a, unsigned long long b) {
    asm("fma.rn.f32x2 %0, %1, %2, %0;" : "+l"(d) : "l"(a), "l"(b));
}
__device__ __forceinline__ float hadd2(unsigned long long v) {
    float lo, hi;
    asm("mov.b64 {%0,%1}, %2;" : "=f"(lo), "=f"(hi) : "l"(v));
    return lo + hi;
}
__device__ __forceinline__ unsigned long long pack2(float lo, float hi) {
    unsigned long long r;
    asm("mov.b64 %0, {%1,%2};" : "=l"(r) : "f"(lo), "f"(hi));
    return r;
}
__device__ __forceinline__ void unpack2(float& lo, float& hi, unsigned long long v) {
    asm("mov.b64 {%0,%1}, %2;" : "=f"(lo), "=f"(hi) : "l"(v));
}
__device__ __forceinline__ float warp_max(float x) {
#pragma unroll
    for (int o = 16; o; o >>= 1) x = fmaxf(x, __shfl_xor_sync(0xffffffffu, x, o));
    return x;
}
__device__ __forceinline__ float warp_sum(float x) {
#pragma unroll
    for (int o = 16; o; o >>= 1) x += __shfl_xor_sync(0xffffffffu, x, o);
    return x;
}

// =====================================================================
// Kernel 1: QK base scores. g_s0[bh,i,j] = (q/8)[bh,i,:] . k[bh,j,:]
// grid 256 = 16 bh x (4 itile x 4 jtile of 128x128), 256 thr, 8x8 micro
// (exact R6 version — 20.7us measured)
// =====================================================================
#define QK_PADI 132
#define QK_SMEM_FLOATS (2*64*QK_PADI)   // 16896 -> 67584 B

__global__ void __launch_bounds__(256, 2)
qk_kernel(const float* __restrict__ q, const float* __restrict__ k)
{
    extern __shared__ float smq[];
    float* qT = smq;                 // [64 d][132]
    float* kT = smq + 64 * QK_PADI;  // [64 d][132]
    const int bid = blockIdx.x;
    const int bh = bid >> 4;
    const int it = (bid >> 2) & 3, jt = bid & 3;
    const int i0 = it * 128, j0 = jt * 128;
    const int tid = threadIdx.x;

    const float* qb = q + ((size_t)bh * LL + i0) * DD;
    const float* kb = k + ((size_t)bh * LL + j0) * DD;
#pragma unroll
    for (int f = tid; f < 128 * 64; f += 256) {
        int i = f >> 6, d = f & 63;
        qT[d * QK_PADI + i] = qb[(size_t)i * DD + d] * TEMPINV;
        kT[d * QK_PADI + i] = kb[(size_t)i * DD + d];
    }
    __syncthreads();

    const int ty = tid >> 4, tx = tid & 15;
    const int il = ty * 8, jl = tx * 8;
    unsigned long long acc[8][4];
#pragma unroll
    for (int r = 0; r < 8; r++)
#pragma unroll
        for (int c = 0; c < 4; c++) acc[r][c] = 0ull;

#pragma unroll 4
    for (int d = 0; d < 64; d++) {
        float4 a0 = *reinterpret_cast<const float4*>(qT + d * QK_PADI + il);
        float4 a1 = *reinterpret_cast<const float4*>(qT + d * QK_PADI + il + 4);
        const ulonglong2* bp = reinterpret_cast<const ulonglong2*>(kT + d * QK_PADI + jl);
        ulonglong2 b01 = bp[0], b23 = bp[1];
        float a[8] = {a0.x,a0.y,a0.z,a0.w,a1.x,a1.y,a1.z,a1.w};
#pragma unroll
        for (int r = 0; r < 8; r++) {
            unsigned long long ar = pack2(a[r], a[r]);
            fma2(acc[r][0], ar, b01.x);
            fma2(acc[r][1], ar, b01.y);
            fma2(acc[r][2], ar, b23.x);
            fma2(acc[r][3], ar, b23.y);
        }
    }

#pragma unroll
    for (int r = 0; r < 8; r++) {
        float c[8];
#pragma unroll
        for (int c2 = 0; c2 < 4; c2++) unpack2(c[2*c2], c[2*c2+1], acc[r][c2]);
        float* dst = g_s0 + ((size_t)bh * LL + i0 + il + r) * LL + j0 + jl;
        float4 v0 = {c[0], c[1], c[2], c[3]};
        float4 v1 = {c[4], c[5], c[6], c[7]};
        *reinterpret_cast<float4*>(dst)     = v0;
        *reinterpret_cast<float4*>(dst + 4) = v1;
    }
}

// =====================================================================
// Kernel 2 (main): adj-score accumulation + softmax + adj_v weighted sum
// grid 256 = (b, i-tile of 4 rows), 512 thr
// R6 compute, 3-stage cp.async pipelines
// =====================================================================
__global__ void __launch_bounds__(NTHR, 1)
main_kernel(const float* __restrict__ q, const float* __restrict__ adjk,
            const float* __restrict__ adjv, const int* __restrict__ mask,
            float* __restrict__ out, float* __restrict__ attn_ext, int write_ext)
{
    extern __shared__ float sm[];
    float* attn = write_ext ? attn_ext : g_attn_fb;

    const int bid  = blockIdx.x;
    const int b    = bid / (LL / TI);
    const int i0   = (bid % (LL / TI)) * TI;
    const int tid  = threadIdx.x;
    const int w    = tid >> 5;
    const int lane = tid & 31;

    float* qs = sm + OFF_QS;
    float* mk = sm + OFF_MK;
    float* r1 = sm + OFF_R1;
    float* r2 = sm + OFF_R2;
    const uint32_t smemU = (uint32_t)__cvta_generic_to_shared(sm);

    // ---- phase 0: qs (scaled q) + mask flags ----
    {
        int d4 = tid & 15, h = (tid >> 4) & 7, ti = tid >> 7;
        float4 val = *reinterpret_cast<const float4*>(
            &q[((size_t)(b * HH + h) * LL + i0 + ti) * DD + d4 * 4]);
        val.x *= TEMPINV; val.y *= TEMPINV; val.z *= TEMPINV; val.w *= TEMPINV;
        reinterpret_cast<float4*>(qs)[(ti * HH + h) * (DD / 4) + d4] = val;
        mk[tid] = (mask[b * LL + tid] != 0) ? 1.0f : 0.0f;
    }

    // warp mapping phase 1: ti, jh (j half of 64), hg (head group of 4)
    const int ti  = w >> 2;
    const int sub = w & 3;
    const int jh  = sub >> 1;
    const int hg  = sub & 1;
    const int h0  = hg * 4;
    const int jj  = jh * 32 + lane;          // 0..63 within tile
    const int rbase = ti * HH + h0;          // row 0..31

    const float* adjk_b = adjk + ((size_t)(b * LL + i0) * LL) * DD;
    const float* adjv_b = adjv + ((size_t)(b * LL + i0) * LL) * DD;

    // prologue: stage phase-1 tiles 0 and 1 (two commit groups)
#pragma unroll
    for (int pt = 0; pt < 2; pt++) {
        const float* srcb = adjk_b + (size_t)pt * 64 * DD;
        const int base = OFF_BUF + pt * SM1_TILE;
#pragma unroll
        for (int s2 = 0; s2 < 8; s2++) {
            int f = tid + s2 * NTHR;
            int d4 = f & 15, jjx = (f >> 4) & 63, ti2 = f >> 10;
            cpa16(smemU + (uint32_t)(base + (ti2 * 64 + jjx) * 68 + d4 * 4) * 4,
                  srcb + (size_t)ti2 * (LL * DD) + (size_t)jjx * DD + d4 * 4);
        }
        CP_COMMIT;
    }

    // init scores from g_s0
    float s[4][8];
#pragma unroll
    for (int hh = 0; hh < 4; hh++)
#pragma unroll
        for (int t = 0; t < 8; t++)
            s[hh][t] = g_s0[((size_t)(b * HH + h0 + hh) * LL + i0 + ti) * LL + t * 64 + jj];

    const ulonglong2* q0p = reinterpret_cast<const ulonglong2*>(qs + (rbase + 0) * DD);
    const ulonglong2* q1p = reinterpret_cast<const ulonglong2*>(qs + (rbase + 1) * DD);
    const ulonglong2* q2p = reinterpret_cast<const ulonglong2*>(qs + (rbase + 2) * DD);
    const ulonglong2* q3p = reinterpret_cast<const ulonglong2*>(qs + (rbase + 3) * DD);

    // ---- phase 1: 8 tiles of 64 j, 3-stage pipeline ----
#pragma unroll
    for (int t = 0; t < 8; t++) {
        if (t < 6) {
            // prefetch tile t+2 into buf (t+2)%3
            const float* srcb = adjk_b + (size_t)(t + 2) * 64 * DD;
            const int base = OFF_BUF + ((t + 2) % 3) * SM1_TILE;
#pragma unroll
            for (int s2 = 0; s2 < 8; s2++) {
                int f = tid + s2 * NTHR;
                int d4 = f & 15, jjx = (f >> 4) & 63, ti2 = f >> 10;
                cpa16(smemU + (uint32_t)(base + (ti2 * 64 + jjx) * 68 + d4 * 4) * 4,
                      srcb + (size_t)ti2 * (LL * DD) + (size_t)jjx * DD + d4 * 4);
            }
            CP_COMMIT;
            CP_WAIT2;      // tile t done; t+1, t+2 may be in flight
        } else if (t == 6) {
            CP_WAIT1;      // tile 6 done; 7 in flight
        } else {
            CP_WAIT0;      // tile 7 done
        }
        __syncthreads();

        const float* bufp = sm + OFF_BUF + (t % 3) * SM1_TILE;
        const ulonglong2* ap = reinterpret_cast<const ulonglong2*>(bufp + (ti * 64 + jj) * 68);
        unsigned long long a0 = 0ull, a1 = 0ull, a2 = 0ull, a3 = 0ull;
#pragma unroll
        for (int d4 = 0; d4 < 16; d4++) {
            ulonglong2 ad = ap[d4];
            ulonglong2 v0 = q0p[d4]; fma2(a0, v0.x, ad.x); fma2(a0, v0.y, ad.y);
            ulonglong2 v1 = q1p[d4]; fma2(a1, v1.x, ad.x); fma2(a1, v1.y, ad.y);
            ulonglong2 v2 = q2p[d4]; fma2(a2, v2.x, ad.x); fma2(a2, v2.y, ad.y);
            ulonglong2 v3 = q3p[d4]; fma2(a3, v3.x, ad.x); fma2(a3, v3.y, ad.y);
        }
        s[0][t] += hadd2(a0); s[1][t] += hadd2(a1);
        s[2][t] += hadd2(a2); s[3][t] += hadd2(a3);
        __syncthreads();
    }

    // prologue: stage phase-2 tiles 0,1 (buffers all dead; softmax overlaps the fetch)
#pragma unroll
    for (int pt = 0; pt < 2; pt++) {
        const float* srcb = adjv_b + (size_t)pt * 64 * DD;
        const int base = OFF_BUF + pt * SM1_TILE;   // phase-2 buf i at same bases
#pragma unroll
        for (int s2 = 0; s2 < 8; s2++) {
            int f = tid + s2 * NTHR;
            int d4 = f & 15, jx = (f >> 4) & 63, ti2 = f >> 10;
            cpa16(smemU + (uint32_t)(base + (ti2 * 64 + jx) * 64 + d4 * 4) * 4,
                  srcb + (size_t)ti2 * (LL * DD) + (size_t)jx * DD + d4 * 4);
        }
        CP_COMMIT;
    }

    // ---- softmax (mask -> max -> exp -> norm) ----
    float m[4] = {-3.4e38f, -3.4e38f, -3.4e38f, -3.4e38f};
#pragma unroll
    for (int t = 0; t < 8; t++) {
        bool live = mk[t * 64 + jj] != 0.0f;
#pragma unroll
        for (int hh = 0; hh < 4; hh++) {
            float x = live ? s[hh][t] : -10000.0f;
            s[hh][t] = x;
            m[hh] = fmaxf(m[hh], x);
        }
    }
#pragma unroll
    for (int hh = 0; hh < 4; hh++) m[hh] = warp_max(m[hh]);
    if (lane == 0) {
#pragma unroll
        for (int hh = 0; hh < 4; hh++) r1[(rbase + hh) * 2 + jh] = m[hh];
    }
    __syncthreads();
#pragma unroll
    for (int hh = 0; hh < 4; hh++)
        m[hh] = fmaxf(r1[(rbase + hh) * 2], r1[(rbase + hh) * 2 + 1]);

    float sum[4] = {0.f, 0.f, 0.f, 0.f};
#pragma unroll
    for (int t = 0; t < 8; t++)
#pragma unroll
        for (int hh = 0; hh < 4; hh++) {
            float e = __expf(s[hh][t] - m[hh]);
            s[hh][t] = e;
            sum[hh] += e;
        }
#pragma unroll
    for (int hh = 0; hh < 4; hh++) sum[hh] = warp_sum(sum[hh]);
    if (lane == 0) {
#pragma unroll
        for (int hh = 0; hh < 4; hh++) r2[(rbase + hh) * 2 + jh] = sum[hh];
    }
    __syncthreads();
    float inv[4];
#pragma unroll
    for (int hh = 0; hh < 4; hh++)
        inv[hh] = 1.0f / (r2[(rbase + hh) * 2] + r2[(rbase + hh) * 2 + 1]);

    // write p to attn (gmem only; phase 2 reads it back via L1/L2-hot LDG)
#pragma unroll
    for (int hh = 0; hh < 4; hh++) {
        float* arow = attn + ((size_t)(b * HH + h0 + hh) * LL + i0 + ti) * LL;
#pragma unroll
        for (int t = 0; t < 8; t++) {
            int j = t * 64 + jj;
            arow[j] = s[hh][t] * inv[hh];
        }
    }
    // make attn writes visible to all warps before phase-2 reads
    __syncthreads();

    // ---- phase 2: out_adj = sum_j p * adj_v, 8 tiles of 64 j, 3-stage ----
    const int ti2w = w >> 2;
    const int js   = w & 3;
    const int l2   = lane * 2;

    const float* arp[8];
#pragma unroll
    for (int r = 0; r < 8; r++)
        arp[r] = attn + ((size_t)(b * HH + r) * LL + i0 + ti2w) * LL;

    float2 o[8];
#pragma unroll
    for (int h = 0; h < 8; h++) { o[h].x = 0.f; o[h].y = 0.f; }

#pragma unroll 1
    for (int t2 = 0; t2 < 8; t2++) {
        if (t2 < 6) {
            const float* srcb = adjv_b + (size_t)(t2 + 2) * 64 * DD;
            const int base = OFF_BUF + ((t2 + 2) % 3) * SM1_TILE;
#pragma unroll
            for (int s2 = 0; s2 < 8; s2++) {
                int f = tid + s2 * NTHR;
                int d4 = f & 15, jx = (f >> 4) & 63, tq = f >> 10;
                cpa16(smemU + (uint32_t)(base + (tq * 64 + jx) * 64 + d4 * 4) * 4,
                      srcb + (size_t)tq * (LL * DD) + (size_t)jx * DD + d4 * 4);
            }
            CP_COMMIT;
            CP_WAIT2;
        } else if (t2 == 6) {
            CP_WAIT1;
        } else {
            CP_WAIT0;
        }
        __syncthreads();

        const float* pb = sm + OFF_BUF + (t2 % 3) * SM1_TILE;
#pragma unroll
        for (int x4 = 0; x4 < 4; x4++) {
            const int jb = js * 16 + x4 * 4;
            const int j  = t2 * 64 + jb;
            float4 p[8];
#pragma unroll
            for (int r = 0; r < 8; r++)
                p[r] = *reinterpret_cast<const float4*>(arp[r] + j);
            float2 av0 = *reinterpret_cast<const float2*>(pb + (ti2w * 64 + jb + 0) * 64 + l2);
            float2 av1 = *reinterpret_cast<const float2*>(pb + (ti2w * 64 + jb + 1) * 64 + l2);
            float2 av2 = *reinterpret_cast<const float2*>(pb + (ti2w * 64 + jb + 2) * 64 + l2);
            float2 av3 = *reinterpret_cast<const float2*>(pb + (ti2w * 64 + jb + 3) * 64 + l2);
#pragma unroll
            for (int r = 0; r < 8; r++) {
                o[r].x += p[r].x * av0.x; o[r].y += p[r].x * av0.y;
                o[r].x += p[r].y * av1.x; o[r].y += p[r].y * av1.y;
                o[r].x += p[r].z * av2.x; o[r].y += p[r].z * av2.y;
                o[r].x += p[r].w * av3.x; o[r].y += p[r].w * av3.y;
            }
        }
        __syncthreads();
    }

    // reduce 4 j-splits via smem (overlay on dead buffer 0 region)
    float* ored = sm + OFF_BUF;   // [4 js][32 rows][64 d] = 8192 floats
#pragma unroll
    for (int h = 0; h < 8; h++)
        *reinterpret_cast<float2*>(ored + ((js * 32 + ti2w * 8 + h) * 64) + l2) = o[h];
    __syncthreads();
    {
        int row = tid >> 4, d4 = tid & 15;
        float4 aa = reinterpret_cast<const float4*>(ored + (0 * 32 + row) * 64)[d4];
        float4 bb = reinterpret_cast<const float4*>(ored + (1 * 32 + row) * 64)[d4];
        float4 cc = reinterpret_cast<const float4*>(ored + (2 * 32 + row) * 64)[d4];
        float4 dd = reinterpret_cast<const float4*>(ored + (3 * 32 + row) * 64)[d4];
        float4 r;
        r.x = aa.x + bb.x + cc.x + dd.x;
        r.y = aa.y + bb.y + cc.y + dd.y;
        r.z = aa.z + bb.z + cc.z + dd.z;
        r.w = aa.w + bb.w + cc.w + dd.w;
        int tio = row / HH, h = row % HH;
        *reinterpret_cast<float4*>(
            &out[((size_t)(b * HH + h) * LL + i0 + tio) * DD + d4 * 4]) = r;
    }
}

// =====================================================================
// Kernel 3: out += attn @ v.  grid 256 = 16 bh x 16 i-tiles of 32
// (exact R6 version)
// =====================================================================
__global__ void __launch_bounds__(256, 4)
av_kernel(const float* __restrict__ v, float* __restrict__ out,
          const float* __restrict__ attn_ext, int write_ext)
{
    __shared__ float aS[2][32 * 32];   // [i][j]
    __shared__ float vS[2][32 * 64];   // [j][d]
    const float* attn = write_ext ? attn_ext : g_attn_fb;

    const int bid = blockIdx.x;
    const int bh  = bid >> 4;
    const int i0  = (bid & 15) * 32;
    const int tid = threadIdx.x;
    const uint32_t aU = (uint32_t)__cvta_generic_to_shared(&aS[0][0]);
    const uint32_t vU = (uint32_t)__cvta_generic_to_shared(&vS[0][0]);

    const float* ab = attn + ((size_t)bh * LL + i0) * LL;
    const float* vb = v + (size_t)bh * LL * DD;

    // stage tile 0
    {
        int i = tid >> 3, c = tid & 7;
        cpa16(aU + (uint32_t)(i * 32 + c * 4) * 4, ab + (size_t)i * LL + c * 4);
#pragma unroll
        for (int s2 = 0; s2 < 2; s2++) {
            int f = tid + s2 * 256;
            int j = f >> 4, d4 = f & 15;
            cpa16(vU + (uint32_t)(j * 64 + d4 * 4) * 4, vb + (size_t)j * DD + d4 * 4);
        }
        CP_COMMIT;
    }

    const int ty = tid >> 5, tx = tid & 31;
    float2 o[4];
#pragma unroll
    for (int r = 0; r < 4; r++) { o[r].x = 0.f; o[r].y = 0.f; }

#pragma unroll 1
    for (int kt = 0; kt < 16; kt++) {
        if (kt < 15) {
            int j0 = (kt + 1) * 32;
            int bsel = (kt + 1) & 1;
            int i = tid >> 3, c = tid & 7;
            cpa16(aU + (uint32_t)(bsel * 1024 + i * 32 + c * 4) * 4,
                  ab + (size_t)i * LL + j0 + c * 4);
#pragma unroll
            for (int s2 = 0; s2 < 2; s2++) {
                int f = tid + s2 * 256;
                int j = f >> 4, d4 = f & 15;
                cpa16(vU + (uint32_t)(bsel * 2048 + j * 64 + d4 * 4) * 4,
                      vb + (size_t)(j0 + j) * DD + d4 * 4);
            }
            CP_COMMIT;
            CP_WAIT1;
        } else {
            CP_WAIT0;
        }
        __syncthreads();

        const float* aT = &aS[kt & 1][0];
        const float* vT = &vS[kt & 1][0];
#pragma unroll 4
        for (int j = 0; j < 32; j++) {
            float2 vv = *reinterpret_cast<const float2*>(vT + j * 64 + tx * 2);
            float p0 = aT[(ty * 4 + 0) * 32 + j];
            float p1 = aT[(ty * 4 + 1) * 32 + j];
            float p2 = aT[(ty * 4 + 2) * 32 + j];
            float p3 = aT[(ty * 4 + 3) * 32 + j];
            o[0].x += p0 * vv.x; o[0].y += p0 * vv.y;
            o[1].x += p1 * vv.x; o[1].y += p1 * vv.y;
            o[2].x += p2 * vv.x; o[2].y += p2 * vv.y;
            o[3].x += p3 * vv.x; o[3].y += p3 * vv.y;
        }
        __syncthreads();
    }

#pragma unroll
    for (int r = 0; r < 4; r++) {
        float2* op = reinterpret_cast<float2*>(
            &out[((size_t)bh * LL + i0 + ty * 4 + r) * DD + tx * 2]);
        float2 cur = *op;
        cur.x += o[r].x; cur.y += o[r].y;
        *op = cur;
    }
}

// =====================================================================
extern "C" void kernel_launch(void* const* d_in, const int* in_sizes, int n_in,
                              void* d_out, int out_size)
{
    const float* q    = (const float*)d_in[0];
    const float* k    = (const float*)d_in[1];
    const float* v    = (const float*)d_in[2];
    const float* adjk = (const float*)d_in[3];
    const float* adjv = (const float*)d_in[4];
    const int*   mask = (const int*)d_in[5];
    float* out = (float*)d_out;

    int write_attn = (out_size >= OUT_ELEMS + ATTN_ELEMS) ? 1 : 0;
    float* attn_ext = out + OUT_ELEMS;

    cudaFuncSetAttribute(qk_kernel, cudaFuncAttributeMaxDynamicSharedMemorySize,
                         QK_SMEM_FLOATS * 4);
    cudaFuncSetAttribute(main_kernel, cudaFuncAttributeMaxDynamicSharedMemorySize,
                         MAIN_SMEM_FLOATS * 4);

    qk_kernel<<<256, 256, QK_SMEM_FLOATS * 4>>>(q, k);
    main_kernel<<<BB * (LL / TI), NTHR, MAIN_SMEM_FLOATS * 4>>>(
        q, adjk, adjv, mask, out, attn_ext, write_attn);
    av_kernel<<<256, 256>>>(v, out, attn_ext, write_attn);
}

// round 10
// speedup vs baseline: 1.2619x; 1.0522x over previous
#include <cuda_runtime.h>
#include <cstdint>

#define BB 2
#define HH 8
#define LL 512
#define DD 64
#define TI 4
#define NTHR 512
#define TEMPINV 0.125f

#define OUT_ELEMS  (BB*HH*LL*DD)
#define ATTN_ELEMS (BB*HH*LL*LL)

// 16 MB scratch for base scores qs@k^T ; 16 MB fallback attn buffer
__device__ float g_s0[ATTN_ELEMS];
__device__ float g_attn_fb[ATTN_ELEMS];

// ---------- main kernel smem layout (floats) ----------
#define OFF_QS   0                  // qs[4][8][64] = 2048
#define OFF_MK   2048               // 512
#define OFF_R1   2560               // 64
#define OFF_R2   2624               // 64
#define OFF_BUF  2688               // double buffers (phase 1 only)
#define SM1_TILE (4*64*68)          // 17408 (phase1 adjk tile, PAD 68)
#define MAIN_SMEM_FLOATS (OFF_BUF + 2*SM1_TILE)   // 37504 -> 150016 B

// ---------- PTX helpers ----------
__device__ __forceinline__ void cpa16(uint32_t dst, const void* src) {
    asm volatile("cp.async.cg.shared.global [%0], [%1], 16;" :: "r"(dst), "l"(src) : "memory");
}
#define CP_COMMIT asm volatile("cp.async.commit_group;" ::: "memory")
#define CP_WAIT1  asm volatile("cp.async.wait_group 1;" ::: "memory")
#define CP_WAIT0  asm volatile("cp.async.wait_group 0;" ::: "memory")

__device__ __forceinline__ void fma2(unsigned long long& d,
                                     unsigned long long a, unsigned long long b) {
    asm("fma.rn.f32x2 %0, %1, %2, %0;" : "+l"(d) : "l"(a), "l"(b));
}
__device__ __forceinline__ float hadd2(unsigned long long v) {
    float lo, hi;
    asm("mov.b64 {%0,%1}, %2;" : "=f"(lo), "=f"(hi) : "l"(v));
    return lo + hi;
}
__device__ __forceinline__ unsigned long long pack2(float lo, float hi) {
    unsigned long long r;
    asm("mov.b64 %0, {%1,%2};" : "=l"(r) : "f"(lo), "f"(hi));
    return r;
}
__device__ __forceinline__ void unpack2(float& lo, float& hi, unsigned long long v) {
    asm("mov.b64 {%0,%1}, %2;" : "=f"(lo), "=f"(hi) : "l"(v));
}
__device__ __forceinline__ float warp_max(float x) {
#pragma unroll
    for (int o = 16; o; o >>= 1) x = fmaxf(x, __shfl_xor_sync(0xffffffffu, x, o));
    return x;
}
__device__ __forceinline__ float warp_sum(float x) {
#pragma unroll
    for (int o = 16; o; o >>= 1) x += __shfl_xor_sync(0xffffffffu, x, o);
    return x;
}

// =====================================================================
// Kernel 1: QK base scores. g_s0[bh,i,j] = (q/8)[bh,i,:] . k[bh,j,:]
// (exact R6 version — 20.7us measured)
// =====================================================================
#define QK_PADI 132
#define QK_SMEM_FLOATS (2*64*QK_PADI)   // 16896 -> 67584 B

__global__ void __launch_bounds__(256, 2)
qk_kernel(const float* __restrict__ q, const float* __restrict__ k)
{
    extern __shared__ float smq[];
    float* qT = smq;                 // [64 d][132]
    float* kT = smq + 64 * QK_PADI;  // [64 d][132]
    const int bid = blockIdx.x;
    const int bh = bid >> 4;
    const int it = (bid >> 2) & 3, jt = bid & 3;
    const int i0 = it * 128, j0 = jt * 128;
    const int tid = threadIdx.x;

    const float* qb = q + ((size_t)bh * LL + i0) * DD;
    const float* kb = k + ((size_t)bh * LL + j0) * DD;
#pragma unroll
    for (int f = tid; f < 128 * 64; f += 256) {
        int i = f >> 6, d = f & 63;
        qT[d * QK_PADI + i] = qb[(size_t)i * DD + d] * TEMPINV;
        kT[d * QK_PADI + i] = kb[(size_t)i * DD + d];
    }
    __syncthreads();

    const int ty = tid >> 4, tx = tid & 15;
    const int il = ty * 8, jl = tx * 8;
    unsigned long long acc[8][4];
#pragma unroll
    for (int r = 0; r < 8; r++)
#pragma unroll
        for (int c = 0; c < 4; c++) acc[r][c] = 0ull;

#pragma unroll 4
    for (int d = 0; d < 64; d++) {
        float4 a0 = *reinterpret_cast<const float4*>(qT + d * QK_PADI + il);
        float4 a1 = *reinterpret_cast<const float4*>(qT + d * QK_PADI + il + 4);
        const ulonglong2* bp = reinterpret_cast<const ulonglong2*>(kT + d * QK_PADI + jl);
        ulonglong2 b01 = bp[0], b23 = bp[1];
        float a[8] = {a0.x,a0.y,a0.z,a0.w,a1.x,a1.y,a1.z,a1.w};
#pragma unroll
        for (int r = 0; r < 8; r++) {
            unsigned long long ar = pack2(a[r], a[r]);
            fma2(acc[r][0], ar, b01.x);
            fma2(acc[r][1], ar, b01.y);
            fma2(acc[r][2], ar, b23.x);
            fma2(acc[r][3], ar, b23.y);
        }
    }

#pragma unroll
    for (int r = 0; r < 8; r++) {
        float c[8];
#pragma unroll
        for (int c2 = 0; c2 < 4; c2++) unpack2(c[2*c2], c[2*c2+1], acc[r][c2]);
        float* dst = g_s0 + ((size_t)bh * LL + i0 + il + r) * LL + j0 + jl;
        float4 v0 = {c[0], c[1], c[2], c[3]};
        float4 v1 = {c[4], c[5], c[6], c[7]};
        *reinterpret_cast<float4*>(dst)     = v0;
        *reinterpret_cast<float4*>(dst + 4) = v1;
    }
}

// =====================================================================
// Kernel 2 (main): adj-score accumulation + softmax + adj_v weighted sum
// grid 256 = (b, i-tile of 4 rows), 512 thr
// R6 phase 1; phase 2 via DIRECT LDG (no smem staging, no barriers)
// =====================================================================
__global__ void __launch_bounds__(NTHR, 1)
main_kernel(const float* __restrict__ q, const float* __restrict__ adjk,
            const float* __restrict__ adjv, const int* __restrict__ mask,
            float* __restrict__ out, float* __restrict__ attn_ext, int write_ext)
{
    extern __shared__ float sm[];
    float* attn = write_ext ? attn_ext : g_attn_fb;

    const int bid  = blockIdx.x;
    const int b    = bid / (LL / TI);
    const int i0   = (bid % (LL / TI)) * TI;
    const int tid  = threadIdx.x;
    const int w    = tid >> 5;
    const int lane = tid & 31;

    float* qs = sm + OFF_QS;
    float* mk = sm + OFF_MK;
    float* r1 = sm + OFF_R1;
    float* r2 = sm + OFF_R2;
    const uint32_t smemU = (uint32_t)__cvta_generic_to_shared(sm);

    // ---- phase 0: qs (scaled q) + mask flags ----
    {
        int d4 = tid & 15, h = (tid >> 4) & 7, ti = tid >> 7;
        float4 val = *reinterpret_cast<const float4*>(
            &q[((size_t)(b * HH + h) * LL + i0 + ti) * DD + d4 * 4]);
        val.x *= TEMPINV; val.y *= TEMPINV; val.z *= TEMPINV; val.w *= TEMPINV;
        reinterpret_cast<float4*>(qs)[(ti * HH + h) * (DD / 4) + d4] = val;
        mk[tid] = (mask[b * LL + tid] != 0) ? 1.0f : 0.0f;
    }

    // warp mapping phase 1: ti, jh (j half of 64), hg (head group of 4)
    const int ti  = w >> 2;
    const int sub = w & 3;
    const int jh  = sub >> 1;
    const int hg  = sub & 1;
    const int h0  = hg * 4;
    const int jj  = jh * 32 + lane;          // 0..63 within tile
    const int rbase = ti * HH + h0;          // row 0..31

    const float* adjk_b = adjk + ((size_t)(b * LL + i0) * LL) * DD;
    const float* adjv_b = adjv + ((size_t)(b * LL + i0) * LL) * DD;

    // prologue: stage phase-1 tile 0
    {
        const float* srcb = adjk_b;
#pragma unroll
        for (int s2 = 0; s2 < 8; s2++) {
            int f = tid + s2 * NTHR;
            int d4 = f & 15, jjx = (f >> 4) & 63, ti2 = f >> 10;
            cpa16(smemU + (uint32_t)(OFF_BUF + (ti2 * 64 + jjx) * 68 + d4 * 4) * 4,
                  srcb + (size_t)ti2 * (LL * DD) + (size_t)jjx * DD + d4 * 4);
        }
        CP_COMMIT;
    }

    // init scores from g_s0
    float s[4][8];
#pragma unroll
    for (int hh = 0; hh < 4; hh++)
#pragma unroll
        for (int t = 0; t < 8; t++)
            s[hh][t] = g_s0[((size_t)(b * HH + h0 + hh) * LL + i0 + ti) * LL + t * 64 + jj];

    const ulonglong2* q0p = reinterpret_cast<const ulonglong2*>(qs + (rbase + 0) * DD);
    const ulonglong2* q1p = reinterpret_cast<const ulonglong2*>(qs + (rbase + 1) * DD);
    const ulonglong2* q2p = reinterpret_cast<const ulonglong2*>(qs + (rbase + 2) * DD);
    const ulonglong2* q3p = reinterpret_cast<const ulonglong2*>(qs + (rbase + 3) * DD);

    // ---- phase 1: 8 tiles of 64 j, double-buffered ----
#pragma unroll
    for (int t = 0; t < 8; t++) {
        if (t < 7) {
            const float* srcb = adjk_b + (size_t)(t + 1) * 64 * DD;
            const int base = OFF_BUF + ((t + 1) & 1) * SM1_TILE;
#pragma unroll
            for (int s2 = 0; s2 < 8; s2++) {
                int f = tid + s2 * NTHR;
                int d4 = f & 15, jjx = (f >> 4) & 63, ti2 = f >> 10;
                cpa16(smemU + (uint32_t)(base + (ti2 * 64 + jjx) * 68 + d4 * 4) * 4,
                      srcb + (size_t)ti2 * (LL * DD) + (size_t)jjx * DD + d4 * 4);
            }
            CP_COMMIT;
            CP_WAIT1;
        } else {
            CP_WAIT0;
        }
        __syncthreads();

        const float* bufp = sm + OFF_BUF + (t & 1) * SM1_TILE;
        const ulonglong2* ap = reinterpret_cast<const ulonglong2*>(bufp + (ti * 64 + jj) * 68);
        unsigned long long a0 = 0ull, a1 = 0ull, a2 = 0ull, a3 = 0ull;
#pragma unroll
        for (int d4 = 0; d4 < 16; d4++) {
            ulonglong2 ad = ap[d4];
            ulonglong2 v0 = q0p[d4]; fma2(a0, v0.x, ad.x); fma2(a0, v0.y, ad.y);
            ulonglong2 v1 = q1p[d4]; fma2(a1, v1.x, ad.x); fma2(a1, v1.y, ad.y);
            ulonglong2 v2 = q2p[d4]; fma2(a2, v2.x, ad.x); fma2(a2, v2.y, ad.y);
            ulonglong2 v3 = q3p[d4]; fma2(a3, v3.x, ad.x); fma2(a3, v3.y, ad.y);
        }
        s[0][t] += hadd2(a0); s[1][t] += hadd2(a1);
        s[2][t] += hadd2(a2); s[3][t] += hadd2(a3);
        __syncthreads();
    }

    // ---- softmax (mask -> max -> exp -> norm) ----
    float m[4] = {-3.4e38f, -3.4e38f, -3.4e38f, -3.4e38f};
#pragma unroll
    for (int t = 0; t < 8; t++) {
        bool live = mk[t * 64 + jj] != 0.0f;
#pragma unroll
        for (int hh = 0; hh < 4; hh++) {
            float x = live ? s[hh][t] : -10000.0f;
            s[hh][t] = x;
            m[hh] = fmaxf(m[hh], x);
        }
    }
#pragma unroll
    for (int hh = 0; hh < 4; hh++) m[hh] = warp_max(m[hh]);
    if (lane == 0) {
#pragma unroll
        for (int hh = 0; hh < 4; hh++) r1[(rbase + hh) * 2 + jh] = m[hh];
    }
    __syncthreads();
#pragma unroll
    for (int hh = 0; hh < 4; hh++)
        m[hh] = fmaxf(r1[(rbase + hh) * 2], r1[(rbase + hh) * 2 + 1]);

    float sum[4] = {0.f, 0.f, 0.f, 0.f};
#pragma unroll
    for (int t = 0; t < 8; t++)
#pragma unroll
        for (int hh = 0; hh < 4; hh++) {
            float e = __expf(s[hh][t] - m[hh]);
            s[hh][t] = e;
            sum[hh] += e;
        }
#pragma unroll
    for (int hh = 0; hh < 4; hh++) sum[hh] = warp_sum(sum[hh]);
    if (lane == 0) {
#pragma unroll
        for (int hh = 0; hh < 4; hh++) r2[(rbase + hh) * 2 + jh] = sum[hh];
    }
    __syncthreads();
    float inv[4];
#pragma unroll
    for (int hh = 0; hh < 4; hh++)
        inv[hh] = 1.0f / (r2[(rbase + hh) * 2] + r2[(rbase + hh) * 2 + 1]);

    // write p to attn (gmem only; phase 2 reads it back via L1/L2-hot LDG)
#pragma unroll
    for (int hh = 0; hh < 4; hh++) {
        float* arow = attn + ((size_t)(b * HH + h0 + hh) * LL + i0 + ti) * LL;
#pragma unroll
        for (int t = 0; t < 8; t++) {
            int j = t * 64 + jj;
            arow[j] = s[hh][t] * inv[hh];
        }
    }
    // make attn writes visible to all warps before phase-2 reads
    __syncthreads();

    // ---- phase 2: out_adj = sum_j p * adj_v — DIRECT LDG, no staging ----
    const int ti2w = w >> 2;
    const int js   = w & 3;
    const int l2   = lane * 2;

    const float* arp[8];
#pragma unroll
    for (int r = 0; r < 8; r++)
        arp[r] = attn + ((size_t)(b * HH + r) * LL + i0 + ti2w) * LL;
    const float* avb = adjv_b + (size_t)ti2w * (LL * DD);

    float2 o[8];
#pragma unroll
    for (int h = 0; h < 8; h++) { o[h].x = 0.f; o[h].y = 0.f; }

#pragma unroll 1
    for (int t2 = 0; t2 < 8; t2++) {
#pragma unroll
        for (int x4 = 0; x4 < 4; x4++) {
            const int jb = js * 16 + x4 * 4;
            const int j  = t2 * 64 + jb;
            float4 p[8];
#pragma unroll
            for (int r = 0; r < 8; r++)
                p[r] = *reinterpret_cast<const float4*>(arp[r] + j);
            float2 av0 = *reinterpret_cast<const float2*>(avb + (size_t)(j + 0) * DD + l2);
            float2 av1 = *reinterpret_cast<const float2*>(avb + (size_t)(j + 1) * DD + l2);
            float2 av2 = *reinterpret_cast<const float2*>(avb + (size_t)(j + 2) * DD + l2);
            float2 av3 = *reinterpret_cast<const float2*>(avb + (size_t)(j + 3) * DD + l2);
#pragma unroll
            for (int r = 0; r < 8; r++) {
                o[r].x += p[r].x * av0.x; o[r].y += p[r].x * av0.y;
                o[r].x += p[r].y * av1.x; o[r].y += p[r].y * av1.y;
                o[r].x += p[r].z * av2.x; o[r].y += p[r].z * av2.y;
                o[r].x += p[r].w * av3.x; o[r].y += p[r].w * av3.y;
            }
        }
    }

    // reduce 4 j-splits via smem (overlay on dead buffer 0 region)
    float* ored = sm + OFF_BUF;   // [4 js][32 rows][64 d] = 8192 floats
#pragma unroll
    for (int h = 0; h < 8; h++)
        *reinterpret_cast<float2*>(ored + ((js * 32 + ti2w * 8 + h) * 64) + l2) = o[h];
    __syncthreads();
    {
        int row = tid >> 4, d4 = tid & 15;
        float4 aa = reinterpret_cast<const float4*>(ored + (0 * 32 + row) * 64)[d4];
        float4 bb = reinterpret_cast<const float4*>(ored + (1 * 32 + row) * 64)[d4];
        float4 cc = reinterpret_cast<const float4*>(ored + (2 * 32 + row) * 64)[d4];
        float4 dd = reinterpret_cast<const float4*>(ored + (3 * 32 + row) * 64)[d4];
        float4 r;
        r.x = aa.x + bb.x + cc.x + dd.x;
        r.y = aa.y + bb.y + cc.y + dd.y;
        r.z = aa.z + bb.z + cc.z + dd.z;
        r.w = aa.w + bb.w + cc.w + dd.w;
        int tio = row / HH, h = row % HH;
        *reinterpret_cast<float4*>(
            &out[((size_t)(b * HH + h) * LL + i0 + tio) * DD + d4 * 4]) = r;
    }
}

// =====================================================================
// Kernel 3: out += attn @ v.  (exact R6 version)
// =====================================================================
__global__ void __launch_bounds__(256, 4)
av_kernel(const float* __restrict__ v, float* __restrict__ out,
          const float* __restrict__ attn_ext, int write_ext)
{
    __shared__ float aS[2][32 * 32];   // [i][j]
    __shared__ float vS[2][32 * 64];   // [j][d]
    const float* attn = write_ext ? attn_ext : g_attn_fb;

    const int bid = blockIdx.x;
    const int bh  = bid >> 4;
    const int i0  = (bid & 15) * 32;
    const int tid = threadIdx.x;
    const uint32_t aU = (uint32_t)__cvta_generic_to_shared(&aS[0][0]);
    const uint32_t vU = (uint32_t)__cvta_generic_to_shared(&vS[0][0]);

    const float* ab = attn + ((size_t)bh * LL + i0) * LL;
    const float* vb = v + (size_t)bh * LL * DD;

    // stage tile 0
    {
        int i = tid >> 3, c = tid & 7;
        cpa16(aU + (uint32_t)(i * 32 + c * 4) * 4, ab + (size_t)i * LL + c * 4);
#pragma unroll
        for (int s2 = 0; s2 < 2; s2++) {
            int f = tid + s2 * 256;
            int j = f >> 4, d4 = f & 15;
            cpa16(vU + (uint32_t)(j * 64 + d4 * 4) * 4, vb + (size_t)j * DD + d4 * 4);
        }
        CP_COMMIT;
    }

    const int ty = tid >> 5, tx = tid & 31;
    float2 o[4];
#pragma unroll
    for (int r = 0; r < 4; r++) { o[r].x = 0.f; o[r].y = 0.f; }

#pragma unroll 1
    for (int kt = 0; kt < 16; kt++) {
        if (kt < 15) {
            int j0 = (kt + 1) * 32;
            int bsel = (kt + 1) & 1;
            int i = tid >> 3, c = tid & 7;
            cpa16(aU + (uint32_t)(bsel * 1024 + i * 32 + c * 4) * 4,
                  ab + (size_t)i * LL + j0 + c * 4);
#pragma unroll
            for (int s2 = 0; s2 < 2; s2++) {
                int f = tid + s2 * 256;
                int j = f >> 4, d4 = f & 15;
                cpa16(vU + (uint32_t)(bsel * 2048 + j * 64 + d4 * 4) * 4,
                      vb + (size_t)(j0 + j) * DD + d4 * 4);
            }
            CP_COMMIT;
            CP_WAIT1;
        } else {
            CP_WAIT0;
        }
        __syncthreads();

        const float* aT = &aS[kt & 1][0];
        const float* vT = &vS[kt & 1][0];
#pragma unroll 4
        for (int j = 0; j < 32; j++) {
            float2 vv = *reinterpret_cast<const float2*>(vT + j * 64 + tx * 2);
            float p0 = aT[(ty * 4 + 0) * 32 + j];
            float p1 = aT[(ty * 4 + 1) * 32 + j];
            float p2 = aT[(ty * 4 + 2) * 32 + j];
            float p3 = aT[(ty * 4 + 3) * 32 + j];
            o[0].x += p0 * vv.x; o[0].y += p0 * vv.y;
            o[1].x += p1 * vv.x; o[1].y += p1 * vv.y;
            o[2].x += p2 * vv.x; o[2].y += p2 * vv.y;
            o[3].x += p3 * vv.x; o[3].y += p3 * vv.y;
        }
        __syncthreads();
    }

#pragma unroll
    for (int r = 0; r < 4; r++) {
        float2* op = reinterpret_cast<float2*>(
            &out[((size_t)bh * LL + i0 + ty * 4 + r) * DD + tx * 2]);
        float2 cur = *op;
        cur.x += o[r].x; cur.y += o[r].y;
        *op = cur;
    }
}

// =====================================================================
extern "C" void kernel_launch(void* const* d_in, const int* in_sizes, int n_in,
                              void* d_out, int out_size)
{
    const float* q    = (const float*)d_in[0];
    const float* k    = (const float*)d_in[1];
    const float* v    = (const float*)d_in[2];
    const float* adjk = (const float*)d_in[3];
    const float* adjv = (const float*)d_in[4];
    const int*   mask = (const int*)d_in[5];
    float* out = (float*)d_out;

    int write_attn = (out_size >= OUT_ELEMS + ATTN_ELEMS) ? 1 : 0;
    float* attn_ext = out + OUT_ELEMS;

    cudaFuncSetAttribute(qk_kernel, cudaFuncAttributeMaxDynamicSharedMemorySize,
                         QK_SMEM_FLOATS * 4);
    cudaFuncSetAttribute(main_kernel, cudaFuncAttributeMaxDynamicSharedMemorySize,
                         MAIN_SMEM_FLOATS * 4);

    qk_kernel<<<256, 256, QK_SMEM_FLOATS * 4>>>(q, k);
    main_kernel<<<BB * (LL / TI), NTHR, MAIN_SMEM_FLOATS * 4>>>(
        q, adjk, adjv, mask, out, attn_ext, write_attn);
    av_kernel<<<256, 256>>>(v, out, attn_ext, write_attn);
}